// round 9
// baseline (speedup 1.0000x reference)
#include <cuda_runtime.h>
#include <math.h>

#define NQ 12
#define DIM 4096
#define NL 4
#define NC 10
#define BATCH 512
#define TPB 512
#define NBLK (BATCH / 2)     // 256 blocks, 2 samples per block (f32x2 lanes)
#define BN_EPS 1e-5f
#define NSWEEP (NL * NQ / 2) // 24

typedef unsigned long long u64;

// Scratch for softmax probs (B x NC) + completion counter. Allocation-free.
__device__ float g_probs[BATCH * NC];
__device__ unsigned g_cnt = 0;

// ---------------- compile-time GF(2) circuit tables ----------------
// storage swizzle: amplitude i lives at slot i ^ (i>>4) (bijective, XOR-linear)
constexpr int csw(int i) { return i ^ (i >> 4); }
constexpr int cctz(int v) { int n = 0; while (!(v & 1)) { v >>= 1; n++; } return n; }

struct Tab {
    int sp[NSWEEP][12];   // per sweep: sw(v1), sw(v2), sw(bas[0..9]) bank-ordered
    int dz[NC];           // swizzled parity masks for <Z_c> with C^4 folded in
};

constexpr Tab make_tab() {
    Tab t{};
    int M[NQ] = {}, Mi[NQ] = {};
    for (int r = 0; r < NQ; r++) { M[r] = 1 << r; Mi[r] = 1 << r; }
    for (int q = 0; q < NQ; q++) {             // CNOT(q, q+1), q ascending
        int pc = NQ - 1 - q, pt = NQ - 1 - ((q + 1) % NQ);
        M[pt] ^= M[pc];
    }
    for (int q = NQ - 1; q >= 0; q--) {        // inverse: reversed order
        int pc = NQ - 1 - q, pt = NQ - 1 - ((q + 1) % NQ);
        Mi[pt] ^= Mi[pc];
    }
    int Mp[NL + 1][NQ] = {}, Mip[NL][NQ] = {};
    int P[NQ] = {}, Pi_[NQ] = {};
    for (int r = 0; r < NQ; r++) { P[r] = 1 << r; Pi_[r] = 1 << r; }
    for (int l = 0; l <= NL; l++) {
        for (int r = 0; r < NQ; r++) Mp[l][r] = P[r];
        if (l < NL) for (int r = 0; r < NQ; r++) Mip[l][r] = Pi_[r];
        int Pn[NQ] = {}, Pin[NQ] = {};
        for (int r = 0; r < NQ; r++) {
            int acc = 0, acci = 0;
            for (int s = 0; s < NQ; s++) {
                if ((M[r]  >> s) & 1) acc  ^= P[s];
                if ((Mi[r] >> s) & 1) acci ^= Pi_[s];
            }
            Pn[r] = acc; Pin[r] = acci;
        }
        for (int r = 0; r < NQ; r++) { P[r] = Pn[r]; Pi_[r] = Pin[r]; }
    }
    for (int idx = 0; idx < NSWEEP; idx++) {
        int l = idx / 6, k = idx % 6;
        int pa = NQ - 1 - 2 * k;
        int pb = NQ - 1 - (2 * k + 1);
        int v1 = 0, v2 = 0;
        for (int r = 0; r < NQ; r++) {
            v1 |= ((Mip[l][r] >> pa) & 1) << r;
            v2 |= ((Mip[l][r] >> pb) & 1) << r;
        }
        int D1 = Mp[l][pa], D2 = Mp[l][pb];
        int p1 = cctz(D1);
        if ((D2 >> p1) & 1) D2 ^= D1;
        int p2 = cctz(D2);
        if ((D1 >> p2) & 1) D1 ^= D2;
        t.sp[idx][0] = csw(v1);
        t.sp[idx][1] = csw(v2);
        int bas[10] = {};
        int freeb = 0xFFF & ~((1 << p1) | (1 << p2));
        for (int jj = 0; jj < 10; jj++) {
            int j = cctz(freeb); freeb &= freeb - 1;
            bas[jj] = (1 << j) ^ (((D1 >> j) & 1) << p1)
                               ^ (((D2 >> j) & 1) << p2);
        }
        // slots 0..3 (lane bits 0..3) get vectors with GF(2)-independent
        // swizzled low nibbles -> conflict-free LDS.64/STS.64 phases
        int out[10] = {}; int ech[4] = {}; int necc = 0, nsel = 0, ntail = 9;
        for (int i = 0; i < 10; i++) {
            int r = csw(bas[i]) & 15;
            for (int j = 0; j < necc; j++) { int rx = r ^ ech[j]; r = rx < r ? rx : r; }
            if (r != 0 && nsel < 4) { ech[necc++] = r; out[nsel++] = bas[i]; }
            else out[ntail--] = bas[i];
        }
        for (int jj = 0; jj < 10; jj++) t.sp[idx][2 + jj] = csw(out[jj]);
    }
    for (int c = 0; c < NC; c++) {
        int d = Mp[NL][NQ - 1 - c];
        t.dz[c] = (d ^ (d << 4) ^ (d << 8)) & 0xFFF;
    }
    return t;
}

__constant__ Tab c_tab = make_tab();

// ---------------- packed f32x2 helpers ----------------
__device__ __forceinline__ u64 fma2(u64 a, u64 b, u64 c) {
    u64 d; asm("fma.rn.f32x2 %0, %1, %2, %3;" : "=l"(d) : "l"(a), "l"(b), "l"(c));
    return d;
}
__device__ __forceinline__ u64 mul2(u64 a, u64 b) {
    u64 d; asm("mul.rn.f32x2 %0, %1, %2;" : "=l"(d) : "l"(a), "l"(b));
    return d;
}
__device__ __forceinline__ u64 add2(u64 a, u64 b) {
    u64 d; asm("add.rn.f32x2 %0, %1, %2;" : "=l"(d) : "l"(a), "l"(b));
    return d;
}
__device__ __forceinline__ u64 pack2(float lo, float hi) {
    u64 d; asm("mov.b64 %0, {%1, %2};" : "=l"(d) : "f"(lo), "f"(hi));
    return d;
}
__device__ __forceinline__ float lo32(u64 v) { return __uint_as_float((unsigned)v); }
__device__ __forceinline__ float hi32(u64 v) { return __uint_as_float((unsigned)(v >> 32)); }
__device__ __forceinline__ u64 shfl_down64(u64 v, int o) {
    unsigned lo = (unsigned)v, hi = (unsigned)(v >> 32);
    lo = __shfl_down_sync(0xffffffffu, lo, o);
    hi = __shfl_down_sync(0xffffffffu, hi, o);
    return ((u64)hi << 32) | lo;
}

// lane-parallel SU(2) gate: lane0 = sample0's gate, lane1 = sample1's.
// U = [[a, b], [-b*, a*]]; 7 per-lane-packed consts (incl. negated variants).
struct PGL { u64 ar, ai, nai, br, nbr, bi, nbi; };

// (a,b) <- U (a,b); amplitudes as separate packed re/im (lane = sample).
// Pure lane-wise FFMA2: no swaps, no cross-lane traffic.
__device__ __forceinline__ void pgl(const PGL& g, u64& are, u64& aim,
                                    u64& bre, u64& bim) {
    u64 nre = mul2(g.ar, are);           // na_re = ar*a_re - ai*a_im + br*b_re - bi*b_im
    nre = fma2(g.nai, aim, nre);
    nre = fma2(g.br,  bre, nre);
    nre = fma2(g.nbi, bim, nre);
    u64 nim = mul2(g.ar, aim);           // na_im = ar*a_im + ai*a_re + br*b_im + bi*b_re
    nim = fma2(g.ai,  are, nim);
    nim = fma2(g.br,  bim, nim);
    nim = fma2(g.bi,  bre, nim);
    u64 ore = mul2(g.nbr, are);          // nb_re = -br*a_re - bi*a_im + ar*b_re + ai*b_im
    ore = fma2(g.nbi, aim, ore);
    ore = fma2(g.ar,  bre, ore);
    ore = fma2(g.ai,  bim, ore);
    u64 oim = mul2(g.nbr, aim);          // nb_im = -br*a_im + bi*a_re + ar*b_im - ai*b_re
    oim = fma2(g.bi,  are, oim);
    oim = fma2(g.ar,  bim, oim);
    oim = fma2(g.nai, bre, oim);
    are = nre; aim = nim; bre = ore; bim = oim;
}

extern __shared__ u64 sdyn[];  // st_re[DIM] ++ st_im[DIM] = 64 KB

__global__ __launch_bounds__(TPB, 2) void vqc_kernel(const float* __restrict__ x,
                                                     const float* __restrict__ w,
                                                     const float* __restrict__ bias,
                                                     const float* __restrict__ gamma,
                                                     const float* __restrict__ beta,
                                                     float* __restrict__ out) {
    u64* st_re = sdyn;
    u64* st_im = sdyn + DIM;
    __shared__ u64 s_ga[NL * NQ][7];     // packed per-lane gate constants
    __shared__ float s_ez[2][NC];
    __shared__ unsigned s_last;

    const int b0 = blockIdx.x * 2;       // samples b0, b0+1 (lanes 0, 1)
    const int tid = threadIdx.x;

    // ---- init state (both lanes |0...0>) ----
    for (int i = tid; i < DIM; i += TPB) {
        st_re[i] = (i == 0) ? pack2(1.0f, 1.0f) : 0ull;   // sw(0)==0
        st_im[i] = 0ull;
    }
    if (tid < 2 * NC) (&s_ez[0][0])[tid] = 0.0f;

    // ---- fused gates U = Rot(w) @ RY(x) for both samples, lane-packed ----
    if (tid < NL * NQ) {
        const int l = tid / NQ, q = tid % NQ;
        const float phi = w[(l * NQ + q) * 3 + 0];
        const float th  = w[(l * NQ + q) * 3 + 1];
        const float om  = w[(l * NQ + q) * 3 + 2];
        float stt, ct; sincosf(0.5f * th, &stt, &ct);
        const float a1 = -0.5f * (phi + om);
        const float a2 =  0.5f * (phi - om);
        float s1, c1, s2, c2;
        sincosf(a1, &s1, &c1);
        sincosf(a2, &s2, &c2);
        const float R00r =  c1 * ct, R00i =  s1 * ct;
        const float R01r = -c2 * stt, R01i = -s2 * stt;
        float2 al[2], be[2];
#pragma unroll
        for (int s = 0; s < 2; s++) {
            const float xh = 0.5f * x[(b0 + s) * NQ + q];
            float sy, cy; sincosf(xh, &sy, &cy);
            al[s] = make_float2( R00r * cy + R01r * sy,  R00i * cy + R01i * sy);
            be[s] = make_float2(-R00r * sy + R01r * cy, -R00i * sy + R01i * cy);
        }
        s_ga[tid][0] = pack2( al[0].x,  al[1].x);
        s_ga[tid][1] = pack2( al[0].y,  al[1].y);
        s_ga[tid][2] = pack2(-al[0].y, -al[1].y);
        s_ga[tid][3] = pack2( be[0].x,  be[1].x);
        s_ga[tid][4] = pack2(-be[0].x, -be[1].x);
        s_ga[tid][5] = pack2( be[0].y,  be[1].y);
        s_ga[tid][6] = pack2(-be[0].y, -be[1].y);
    }
    __syncthreads();

    // ---- 24 two-qubit sweeps (CNOT rings folded into masks) ----
    for (int swp = 0; swp < NSWEEP; swp++) {
        const int l = swp / 6, k = swp % 6;
        const int sv1  = c_tab.sp[swp][0];
        const int sv2  = c_tab.sp[swp][1];
        const int sv12 = sv1 ^ sv2;
        const int sb9  = c_tab.sp[swp][11];

        // swizzled base slot for this thread (tid bits 0..8 -> bas 0..8)
        int base = 0;
#pragma unroll
        for (int jj = 0; jj < 9; jj++)
            base ^= ((tid >> jj) & 1) ? c_tab.sp[swp][2 + jj] : 0;

        const u64* gb = s_ga[l * NQ + 2 * k + 1];
        const u64* ga = s_ga[l * NQ + 2 * k];
        const PGL Gb = {gb[0], gb[1], gb[2], gb[3], gb[4], gb[5], gb[6]};
        const PGL Ga = {ga[0], ga[1], ga[2], ga[3], ga[4], ga[5], ga[6]};

#pragma unroll
        for (int u = 0; u < 2; u++) {
            const int j00 = u ? (base ^ sb9) : base;
            const int j01 = j00 ^ sv2;
            const int j10 = j00 ^ sv1;
            const int j11 = j00 ^ sv12;
            u64 re00 = st_re[j00], im00 = st_im[j00];
            u64 re01 = st_re[j01], im01 = st_im[j01];
            u64 re10 = st_re[j10], im10 = st_im[j10];
            u64 re11 = st_re[j11], im11 = st_im[j11];
            pgl(Gb, re00, im00, re01, im01);   // U_b on qubit 2k+1
            pgl(Gb, re10, im10, re11, im11);
            pgl(Ga, re00, im00, re10, im10);   // U_a on qubit 2k
            pgl(Ga, re01, im01, re11, im11);
            st_re[j00] = re00; st_im[j00] = im00;
            st_re[j01] = re01; st_im[j01] = im01;
            st_re[j10] = re10; st_im[j10] = im10;
            st_re[j11] = re11; st_im[j11] = im11;
        }
        __syncthreads();
    }

    // ---- measurement: <Z_c> for both lanes simultaneously ----
    const u64 ONEP = 0x3F8000003F800000ull, ONEN = 0xBF800000BF800000ull;
    u64 ez[NC];
#pragma unroll
    for (int c = 0; c < NC; c++) ez[c] = 0ull;
    for (int s = tid; s < DIM; s += TPB) {
        const u64 re = st_re[s], im = st_im[s];
        const u64 p = fma2(re, re, mul2(im, im));
#pragma unroll
        for (int c = 0; c < NC; c++) {
            const u64 sgn = (__popc(s & c_tab.dz[c]) & 1) ? ONEN : ONEP;
            ez[c] = fma2(p, sgn, ez[c]);
        }
    }
#pragma unroll
    for (int c = 0; c < NC; c++) {
        u64 v = ez[c];
        for (int o = 16; o > 0; o >>= 1) v = add2(v, shfl_down64(v, o));
        if ((tid & 31) == 0) {
            atomicAdd(&s_ez[0][c], lo32(v));
            atomicAdd(&s_ez[1][c], hi32(v));
        }
    }
    __syncthreads();

    // ---- softmax(expz + bias): thread 0 -> sample b0, thread 1 -> b0+1 ----
    if (tid < 2) {
        float z[NC];
        float m = -1e30f;
#pragma unroll
        for (int c = 0; c < NC; c++) {
            z[c] = s_ez[tid][c] + bias[c];
            m = fmaxf(m, z[c]);
        }
        float sum = 0.0f;
#pragma unroll
        for (int c = 0; c < NC; c++) {
            z[c] = expf(z[c] - m);
            sum += z[c];
        }
        const float inv = 1.0f / sum;
#pragma unroll
        for (int c = 0; c < NC; c++) g_probs[(b0 + tid) * NC + c] = z[c] * inv;
    }
    __syncthreads();
    if (tid == 0) {
        __threadfence();
        s_last = atomicAdd(&g_cnt, 1u);
    }
    __syncthreads();

    // ---- BN epilogue: performed entirely by the last-arriving block ----
    if (s_last == NBLK - 1u) {
        if (tid == 0) g_cnt = 0;          // reset for next (graph-replayed) call
        __threadfence();                  // make all blocks' g_probs reads fresh

        __shared__ float smu[NC], srs[NC];
        const int wid = tid >> 5, lid = tid & 31;
        if (wid < NC) {
            const int c = wid;
            float s = 0.0f, q = 0.0f;
            for (int t2 = lid; t2 < BATCH; t2 += 32) {
                const float p = g_probs[t2 * NC + c];
                s += p; q += p * p;
            }
            for (int o = 16; o > 0; o >>= 1) {
                s += __shfl_down_sync(0xffffffffu, s, o);
                q += __shfl_down_sync(0xffffffffu, q, o);
            }
            if (lid == 0) {
                const float mu = s / (float)BATCH;
                smu[c] = mu;
                srs[c] = rsqrtf(q / (float)BATCH - mu * mu + BN_EPS);
            }
        }
        __syncthreads();
        for (int i = tid; i < BATCH * NC; i += TPB) {
            const int c = i % NC;
            out[i] = (g_probs[i] - smu[c]) * srs[c] * gamma[c] + beta[c];
        }
    }
}

extern "C" void kernel_launch(void* const* d_in, const int* in_sizes, int n_in,
                              void* d_out, int out_size) {
    const float* x      = (const float*)d_in[0];  // (512, 12)
    const float* wts    = (const float*)d_in[1];  // (4, 12, 3)
    const float* bias   = (const float*)d_in[2];  // (10,)
    const float* gamma  = (const float*)d_in[3];  // (10,)
    const float* beta   = (const float*)d_in[4];  // (10,)
    float* out = (float*)d_out;                   // (512, 10)

    const int smem_bytes = 2 * DIM * (int)sizeof(u64);   // 64 KB dynamic
    cudaFuncSetAttribute(vqc_kernel,
                         cudaFuncAttributeMaxDynamicSharedMemorySize, smem_bytes);
    vqc_kernel<<<NBLK, TPB, smem_bytes>>>(x, wts, bias, gamma, beta, out);
}

// round 10
// speedup vs baseline: 1.2450x; 1.2450x over previous
#include <cuda_runtime.h>
#include <math.h>

#define NQ 12
#define DIM 4096
#define NL 4
#define NC 10
#define BATCH 512
#define TPB 512
#define NBLK (BATCH / 2)     // 256 blocks, 2 samples per block (f32x2 lanes)
#define BN_EPS 1e-5f
#define NSWEEP (NL * 4)      // 16 three-qubit sweeps

typedef unsigned long long u64;

// Scratch for softmax probs (B x NC) + completion counter. Allocation-free.
__device__ float g_probs[BATCH * NC];
__device__ unsigned g_cnt = 0;

// ---------------- compile-time GF(2) circuit tables ----------------
// storage swizzle: amplitude i lives at slot i ^ (i>>4) (bijective, XOR-linear)
constexpr int csw(int i) { return i ^ (i >> 4); }
constexpr int cctz(int v) { int n = 0; while (!(v & 1)) { v >>= 1; n++; } return n; }
constexpr int cmsb(int v) { int n = -1; while (v) { v >>= 1; n++; } return n; }

// echelon insert: ech indexed by MSB position (0 = empty slot).
// Returns true (and stores) iff v independent of current set.
constexpr bool ins_ech(int* ech, int v) {
    while (v) {
        const int m = cmsb(v);
        if (!ech[m]) { ech[m] = v; return true; }
        v ^= ech[m];
    }
    return false;
}

struct Tab {
    int sp[NSWEEP][12];   // per sweep: sw(v1), sw(v2), sw(v3), sw(bas[0..8])
    int dz[NC];           // swizzled parity masks for <Z_c> with C^4 folded in
};

constexpr Tab make_tab() {
    Tab t{};
    int M[NQ] = {}, Mi[NQ] = {};
    for (int r = 0; r < NQ; r++) { M[r] = 1 << r; Mi[r] = 1 << r; }
    for (int q = 0; q < NQ; q++) {             // CNOT(q, q+1), q ascending
        int pc = NQ - 1 - q, pt = NQ - 1 - ((q + 1) % NQ);
        M[pt] ^= M[pc];
    }
    for (int q = NQ - 1; q >= 0; q--) {        // inverse: reversed order
        int pc = NQ - 1 - q, pt = NQ - 1 - ((q + 1) % NQ);
        Mi[pt] ^= Mi[pc];
    }
    int Mp[NL + 1][NQ] = {}, Mip[NL][NQ] = {};
    int P[NQ] = {}, Pi_[NQ] = {};
    for (int r = 0; r < NQ; r++) { P[r] = 1 << r; Pi_[r] = 1 << r; }
    for (int l = 0; l <= NL; l++) {
        for (int r = 0; r < NQ; r++) Mp[l][r] = P[r];
        if (l < NL) for (int r = 0; r < NQ; r++) Mip[l][r] = Pi_[r];
        int Pn[NQ] = {}, Pin[NQ] = {};
        for (int r = 0; r < NQ; r++) {
            int acc = 0, acci = 0;
            for (int s = 0; s < NQ; s++) {
                if ((M[r]  >> s) & 1) acc  ^= P[s];
                if ((Mi[r] >> s) & 1) acci ^= Pi_[s];
            }
            Pn[r] = acc; Pin[r] = acci;
        }
        for (int r = 0; r < NQ; r++) { P[r] = Pn[r]; Pi_[r] = Pin[r]; }
    }
    // per-sweep: 3 qubits (3g, 3g+1, 3g+2) at layer l
    for (int idx = 0; idx < NSWEEP; idx++) {
        const int l = idx / 4, g = idx % 4;
        int pbit[3] = {}, v[3] = {}, D[3] = {};
        for (int j = 0; j < 3; j++) {
            const int q = 3 * g + j;
            pbit[j] = NQ - 1 - q;
            for (int r = 0; r < NQ; r++)
                v[j] |= ((Mip[l][r] >> pbit[j]) & 1) << r;   // column of M^{-l}
            D[j] = Mp[l][pbit[j]];                           // dual: row of M^l
        }
        // RREF of the 3 duals -> pivots pv[j], each appearing in only its row
        int pv[3] = {};
        for (int j = 0; j < 3; j++) {
            pv[j] = cctz(D[j]);
            for (int i = 0; i < 3; i++)
                if (i != j && ((D[i] >> pv[j]) & 1)) D[i] ^= D[j];
        }
        // null-space basis (9 vectors)
        int bas[9] = {}; int nb = 0;
        const int pmask = (1 << pv[0]) | (1 << pv[1]) | (1 << pv[2]);
        for (int j = 0; j < NQ; j++) {
            if ((pmask >> j) & 1) continue;
            bas[nb++] = (1 << j) ^ (((D[0] >> j) & 1) << pv[0])
                                 ^ (((D[1] >> j) & 1) << pv[1])
                                 ^ (((D[2] >> j) & 1) << pv[2]);
        }
        // bank-aware basis: greedily pick 4 combos with GF(2)-independent
        // swizzled low nibbles (lane bits 0..3 -> conflict-free LDS.64 phases),
        // then complete to a full rank-9 basis.
        int sel[9] = {}; int nsel = 0;
        int echn[4] = {};            // nibble echelon (by MSB 0..3)
        int ech12[12] = {};          // 12-bit echelon for chosen set
        for (int c = 1; c < 512 && nsel < 4; c++) {
            int vv = 0;
            for (int bb = 0; bb < 9; bb++) if ((c >> bb) & 1) vv ^= bas[bb];
            int tmpn[4] = {echn[0], echn[1], echn[2], echn[3]};
            if (!ins_ech(tmpn, csw(vv) & 15)) continue;       // nibble dependent
            int tmp12[12] = {};
            for (int ii = 0; ii < 12; ii++) tmp12[ii] = ech12[ii];
            if (!ins_ech(tmp12, vv)) continue;                // 12-bit dependent
            for (int ii = 0; ii < 4;  ii++) echn[ii]  = tmpn[ii];
            for (int ii = 0; ii < 12; ii++) ech12[ii] = tmp12[ii];
            sel[nsel++] = vv;
        }
        for (int bb = 0; bb < 9 && nsel < 9; bb++)
            if (ins_ech(ech12, bas[bb])) sel[nsel++] = bas[bb];
        t.sp[idx][0] = csw(v[0]);
        t.sp[idx][1] = csw(v[1]);
        t.sp[idx][2] = csw(v[2]);
        for (int jj = 0; jj < 9; jj++) t.sp[idx][3 + jj] = csw(sel[jj]);
    }
    for (int c = 0; c < NC; c++) {
        const int d = Mp[NL][NQ - 1 - c];
        t.dz[c] = (d ^ (d << 4) ^ (d << 8)) & 0xFFF;
    }
    return t;
}

__constant__ Tab c_tab = make_tab();

// ---------------- packed f32x2 helpers ----------------
__device__ __forceinline__ u64 fma2(u64 a, u64 b, u64 c) {
    u64 d; asm("fma.rn.f32x2 %0, %1, %2, %3;" : "=l"(d) : "l"(a), "l"(b), "l"(c));
    return d;
}
__device__ __forceinline__ u64 mul2(u64 a, u64 b) {
    u64 d; asm("mul.rn.f32x2 %0, %1, %2;" : "=l"(d) : "l"(a), "l"(b));
    return d;
}
__device__ __forceinline__ u64 add2(u64 a, u64 b) {
    u64 d; asm("add.rn.f32x2 %0, %1, %2;" : "=l"(d) : "l"(a), "l"(b));
    return d;
}
__device__ __forceinline__ u64 pack2(float lo, float hi) {
    u64 d; asm("mov.b64 %0, {%1, %2};" : "=l"(d) : "f"(lo), "f"(hi));
    return d;
}
__device__ __forceinline__ float lo32(u64 v) { return __uint_as_float((unsigned)v); }
__device__ __forceinline__ float hi32(u64 v) { return __uint_as_float((unsigned)(v >> 32)); }
__device__ __forceinline__ u64 shfl_down64(u64 v, int o) {
    unsigned lo = (unsigned)v, hi = (unsigned)(v >> 32);
    lo = __shfl_down_sync(0xffffffffu, lo, o);
    hi = __shfl_down_sync(0xffffffffu, hi, o);
    return ((u64)hi << 32) | lo;
}

// lane-parallel SU(2) gate: lane0 = sample0's gate, lane1 = sample1's.
struct PGL { u64 ar, ai, nai, br, nbr, bi, nbi; };

// (a,b) <- U (a,b); amplitudes as separate packed re/im (lane = sample).
__device__ __forceinline__ void pgl(const PGL& g, u64& are, u64& aim,
                                    u64& bre, u64& bim) {
    u64 nre = mul2(g.ar, are);
    nre = fma2(g.nai, aim, nre);
    nre = fma2(g.br,  bre, nre);
    nre = fma2(g.nbi, bim, nre);
    u64 nim = mul2(g.ar, aim);
    nim = fma2(g.ai,  are, nim);
    nim = fma2(g.br,  bim, nim);
    nim = fma2(g.bi,  bre, nim);
    u64 ore = mul2(g.nbr, are);
    ore = fma2(g.nbi, aim, ore);
    ore = fma2(g.ar,  bre, ore);
    ore = fma2(g.ai,  bim, ore);
    u64 oim = mul2(g.nbr, aim);
    oim = fma2(g.bi,  are, oim);
    oim = fma2(g.ar,  bim, oim);
    oim = fma2(g.nai, bre, oim);
    are = nre; aim = nim; bre = ore; bim = oim;
}
__device__ __forceinline__ PGL ldpg(const u64* p) {
    PGL g = {p[0], p[1], p[2], p[3], p[4], p[5], p[6]};
    return g;
}

extern __shared__ u64 sdyn[];  // st_re[DIM] ++ st_im[DIM] = 64 KB

__global__ __launch_bounds__(TPB, 2) void vqc_kernel(const float* __restrict__ x,
                                                     const float* __restrict__ w,
                                                     const float* __restrict__ bias,
                                                     const float* __restrict__ gamma,
                                                     const float* __restrict__ beta,
                                                     float* __restrict__ out) {
    u64* st_re = sdyn;
    u64* st_im = sdyn + DIM;
    __shared__ u64 s_ga[NL * NQ][7];     // packed per-lane gate constants
    __shared__ float s_ez[2][NC];
    __shared__ unsigned s_last;

    const int b0 = blockIdx.x * 2;       // samples b0, b0+1 (lanes 0, 1)
    const int tid = threadIdx.x;

    // ---- init state (both lanes |0...0>) ----
    for (int i = tid; i < DIM; i += TPB) {
        st_re[i] = (i == 0) ? pack2(1.0f, 1.0f) : 0ull;   // sw(0)==0
        st_im[i] = 0ull;
    }
    if (tid < 2 * NC) (&s_ez[0][0])[tid] = 0.0f;

    // ---- fused gates U = Rot(w) @ RY(x) for both samples, lane-packed ----
    if (tid < NL * NQ) {
        const int l = tid / NQ, q = tid % NQ;
        const float phi = w[(l * NQ + q) * 3 + 0];
        const float th  = w[(l * NQ + q) * 3 + 1];
        const float om  = w[(l * NQ + q) * 3 + 2];
        float stt, ct; sincosf(0.5f * th, &stt, &ct);
        const float a1 = -0.5f * (phi + om);
        const float a2 =  0.5f * (phi - om);
        float s1, c1, s2, c2;
        sincosf(a1, &s1, &c1);
        sincosf(a2, &s2, &c2);
        const float R00r =  c1 * ct, R00i =  s1 * ct;
        const float R01r = -c2 * stt, R01i = -s2 * stt;
        float2 al[2], be[2];
#pragma unroll
        for (int s = 0; s < 2; s++) {
            const float xh = 0.5f * x[(b0 + s) * NQ + q];
            float sy, cy; sincosf(xh, &sy, &cy);
            al[s] = make_float2( R00r * cy + R01r * sy,  R00i * cy + R01i * sy);
            be[s] = make_float2(-R00r * sy + R01r * cy, -R00i * sy + R01i * cy);
        }
        s_ga[tid][0] = pack2( al[0].x,  al[1].x);
        s_ga[tid][1] = pack2( al[0].y,  al[1].y);
        s_ga[tid][2] = pack2(-al[0].y, -al[1].y);
        s_ga[tid][3] = pack2( be[0].x,  be[1].x);
        s_ga[tid][4] = pack2(-be[0].x, -be[1].x);
        s_ga[tid][5] = pack2( be[0].y,  be[1].y);
        s_ga[tid][6] = pack2(-be[0].y, -be[1].y);
    }
    __syncthreads();

    // ---- 16 three-qubit sweeps (CNOT rings folded into masks) ----
    for (int swp = 0; swp < NSWEEP; swp++) {
        const int l = swp >> 2, g = swp & 3;
        const int sv1 = c_tab.sp[swp][0];
        const int sv2 = c_tab.sp[swp][1];
        const int sv3 = c_tab.sp[swp][2];

        // swizzled base slot for this thread (tid bits 0..8 -> bas 0..8)
        int base = 0;
#pragma unroll
        for (int jj = 0; jj < 9; jj++)
            base ^= ((tid >> jj) & 1) ? c_tab.sp[swp][3 + jj] : 0;

        int j[8];
#pragma unroll
        for (int m = 0; m < 8; m++)
            j[m] = base ^ ((m & 1) ? sv1 : 0) ^ ((m & 2) ? sv2 : 0)
                        ^ ((m & 4) ? sv3 : 0);

        u64 re[8], im[8];
#pragma unroll
        for (int m = 0; m < 8; m++) { re[m] = st_re[j[m]]; im[m] = st_im[j[m]]; }

        {   // gate on qubit 3g+2 (mask v3): pairs (m, m^4) -- 4 independent
            const PGL G = ldpg(s_ga[l * NQ + 3 * g + 2]);
            pgl(G, re[0], im[0], re[4], im[4]);
            pgl(G, re[1], im[1], re[5], im[5]);
            pgl(G, re[2], im[2], re[6], im[6]);
            pgl(G, re[3], im[3], re[7], im[7]);
        }
        {   // gate on qubit 3g+1 (mask v2): pairs (m, m^2)
            const PGL G = ldpg(s_ga[l * NQ + 3 * g + 1]);
            pgl(G, re[0], im[0], re[2], im[2]);
            pgl(G, re[1], im[1], re[3], im[3]);
            pgl(G, re[4], im[4], re[6], im[6]);
            pgl(G, re[5], im[5], re[7], im[7]);
        }
        {   // gate on qubit 3g (mask v1): pairs (m, m^1)
            const PGL G = ldpg(s_ga[l * NQ + 3 * g + 0]);
            pgl(G, re[0], im[0], re[1], im[1]);
            pgl(G, re[2], im[2], re[3], im[3]);
            pgl(G, re[4], im[4], re[5], im[5]);
            pgl(G, re[6], im[6], re[7], im[7]);
        }

#pragma unroll
        for (int m = 0; m < 8; m++) { st_re[j[m]] = re[m]; st_im[j[m]] = im[m]; }
        __syncthreads();
    }

    // ---- measurement: <Z_c> for both lanes simultaneously ----
    const u64 ONEP = 0x3F8000003F800000ull, ONEN = 0xBF800000BF800000ull;
    u64 ez[NC];
#pragma unroll
    for (int c = 0; c < NC; c++) ez[c] = 0ull;
    for (int s = tid; s < DIM; s += TPB) {
        const u64 re = st_re[s], im = st_im[s];
        const u64 p = fma2(re, re, mul2(im, im));
#pragma unroll
        for (int c = 0; c < NC; c++) {
            const u64 sgn = (__popc(s & c_tab.dz[c]) & 1) ? ONEN : ONEP;
            ez[c] = fma2(p, sgn, ez[c]);
        }
    }
#pragma unroll
    for (int c = 0; c < NC; c++) {
        u64 v = ez[c];
        for (int o = 16; o > 0; o >>= 1) v = add2(v, shfl_down64(v, o));
        if ((tid & 31) == 0) {
            atomicAdd(&s_ez[0][c], lo32(v));
            atomicAdd(&s_ez[1][c], hi32(v));
        }
    }
    __syncthreads();

    // ---- softmax(expz + bias): thread 0 -> sample b0, thread 1 -> b0+1 ----
    if (tid < 2) {
        float z[NC];
        float m = -1e30f;
#pragma unroll
        for (int c = 0; c < NC; c++) {
            z[c] = s_ez[tid][c] + bias[c];
            m = fmaxf(m, z[c]);
        }
        float sum = 0.0f;
#pragma unroll
        for (int c = 0; c < NC; c++) {
            z[c] = expf(z[c] - m);
            sum += z[c];
        }
        const float inv = 1.0f / sum;
#pragma unroll
        for (int c = 0; c < NC; c++) g_probs[(b0 + tid) * NC + c] = z[c] * inv;
    }
    __syncthreads();
    if (tid == 0) {
        __threadfence();
        s_last = atomicAdd(&g_cnt, 1u);
    }
    __syncthreads();

    // ---- BN epilogue: performed entirely by the last-arriving block ----
    if (s_last == NBLK - 1u) {
        if (tid == 0) g_cnt = 0;          // reset for next (graph-replayed) call
        __threadfence();                  // make all blocks' g_probs reads fresh

        __shared__ float smu[NC], srs[NC];
        const int wid = tid >> 5, lid = tid & 31;
        if (wid < NC) {
            const int c = wid;
            float s = 0.0f, q = 0.0f;
            for (int t2 = lid; t2 < BATCH; t2 += 32) {
                const float p = g_probs[t2 * NC + c];
                s += p; q += p * p;
            }
            for (int o = 16; o > 0; o >>= 1) {
                s += __shfl_down_sync(0xffffffffu, s, o);
                q += __shfl_down_sync(0xffffffffu, q, o);
            }
            if (lid == 0) {
                const float mu = s / (float)BATCH;
                smu[c] = mu;
                srs[c] = rsqrtf(q / (float)BATCH - mu * mu + BN_EPS);
            }
        }
        __syncthreads();
        for (int i = tid; i < BATCH * NC; i += TPB) {
            const int c = i % NC;
            out[i] = (g_probs[i] - smu[c]) * srs[c] * gamma[c] + beta[c];
        }
    }
}

extern "C" void kernel_launch(void* const* d_in, const int* in_sizes, int n_in,
                              void* d_out, int out_size) {
    const float* x      = (const float*)d_in[0];  // (512, 12)
    const float* wts    = (const float*)d_in[1];  // (4, 12, 3)
    const float* bias   = (const float*)d_in[2];  // (10,)
    const float* gamma  = (const float*)d_in[3];  // (10,)
    const float* beta   = (const float*)d_in[4];  // (10,)
    float* out = (float*)d_out;                   // (512, 10)

    const int smem_bytes = 2 * DIM * (int)sizeof(u64);   // 64 KB dynamic
    cudaFuncSetAttribute(vqc_kernel,
                         cudaFuncAttributeMaxDynamicSharedMemorySize, smem_bytes);
    vqc_kernel<<<NBLK, TPB, smem_bytes>>>(x, wts, bias, gamma, beta, out);
}